// round 1
// baseline (speedup 1.0000x reference)
#include <cuda_runtime.h>
#include <cstdint>
#include <cstddef>

// ---------------------------------------------------------------------------
// NonLocalBlock: B=16, C=64, H=W=64, C1=8, C2=32
// out = gamma * conv1x1(attn_out, w_last, b_last) + x
// attn_out[b,n,:] = softmax_m( delta[b,n,:] . K[b,:,m] ) @ V[b,m,:]
//   delta = conv1x1(x, w_delta)                       [B,4096,8]
//   K     = gathered pooled conv1x1(x, w_phi)         [B,8,1024]  (batch-mix quirk)
//   V     = pooled conv1x1(x, w_g)                    [B,1024,32]
// ---------------------------------------------------------------------------

#define DINL __device__ __forceinline__

// packed f32x2 helpers (sm_103a: fma.rn.f32x2 doubles fp32 FMA throughput/instr)
DINL unsigned long long pk2(float lo, float hi) {
    unsigned long long r;
    asm("mov.b64 %0, {%1, %2};" : "=l"(r) : "f"(lo), "f"(hi));
    return r;
}
DINL void upk2(unsigned long long v, float& lo, float& hi) {
    asm("mov.b64 {%0, %1}, %2;" : "=f"(lo), "=f"(hi) : "l"(v));
}
DINL unsigned long long fma2(unsigned long long a, unsigned long long b, unsigned long long c) {
    unsigned long long d;
    asm("fma.rn.f32x2 %0, %1, %2, %3;" : "=l"(d) : "l"(a), "l"(b), "l"(c));
    return d;
}
DINL unsigned long long mul2(unsigned long long a, unsigned long long b) {
    unsigned long long d;
    asm("mul.rn.f32x2 %0, %1, %2;" : "=l"(d) : "l"(a), "l"(b));
    return d;
}

// scratch (no allocation allowed -> __device__ globals)
__device__ float g_delta[16 * 4096 * 8];   // [b][n][8]
__device__ float g_phiP [16 * 8 * 1024];   // [b][c1][1024]  (pooled, pre-gather)
__device__ float g_gP   [16 * 1024 * 32];  // [b][m][32]     (pooled)

// ---------------------------------------------------------------------------
// Kernel 1: fused 3x conv1x1 (48 output channels) + 2x2 maxpool for phi/g.
// One thread per pooled site (2x2 input pixels). grid (4,16), 256 threads.
// ---------------------------------------------------------------------------
__global__ __launch_bounds__(256, 1) void conv_pool_kernel(
    const float* __restrict__ x,
    const float* __restrict__ w_delta, const float* __restrict__ b_delta,
    const float* __restrict__ w_phi,   const float* __restrict__ b_phi,
    const float* __restrict__ w_g,     const float* __restrict__ b_g)
{
    __shared__ ulonglong2 ws[64][12];   // [c][pair of 48 outputs]: o 0-7 delta, 8-15 phi, 16-47 g
    __shared__ float bias[48];
    const int tid = threadIdx.x;

    for (int i = tid; i < 3072; i += 256) {
        int c = i / 48, o = i - c * 48;
        float w;
        if (o < 8)       w = w_delta[o * 64 + c];
        else if (o < 16) w = w_phi[(o - 8) * 64 + c];
        else             w = w_g[(o - 16) * 64 + c];
        ((float*)&ws[c][0])[o] = w;
    }
    if (tid < 48)
        bias[tid] = (tid < 8) ? b_delta[tid] : (tid < 16) ? b_phi[tid - 8] : b_g[tid - 16];
    __syncthreads();

    const int b  = blockIdx.y;
    const int q  = blockIdx.x * 256 + tid;  // pooled site 0..1023
    const int qy = q >> 5, qx = q & 31;

    float pphi[8], pg[32];
#pragma unroll
    for (int j = 0; j < 8; j++)  pphi[j] = -3.0e38f;
#pragma unroll
    for (int j = 0; j < 32; j++) pg[j]   = -3.0e38f;

#pragma unroll
    for (int ry = 0; ry < 2; ry++) {
        const int row = 2 * qy + ry;
        const float* xp = x + (size_t)b * 262144 + row * 64 + 2 * qx;
        unsigned long long a0[24], a1[24];  // 48 outputs for the two columns
#pragma unroll
        for (int k = 0; k < 24; k++) { a0[k] = 0ull; a1[k] = 0ull; }

#pragma unroll 4
        for (int c = 0; c < 64; c++) {
            float2 xv = *(const float2*)(xp + c * 4096);   // coalesced across warp
            unsigned long long x0 = pk2(xv.x, xv.x);
            unsigned long long x1 = pk2(xv.y, xv.y);
#pragma unroll
            for (int k = 0; k < 12; k++) {
                ulonglong2 w = ws[c][k];                   // broadcast LDS.128
                a0[2*k]   = fma2(w.x, x0, a0[2*k]);
                a0[2*k+1] = fma2(w.y, x0, a0[2*k+1]);
                a1[2*k]   = fma2(w.x, x1, a1[2*k]);
                a1[2*k+1] = fma2(w.y, x1, a1[2*k+1]);
            }
        }

        float f0[48], f1[48];
#pragma unroll
        for (int k = 0; k < 24; k++) {
            upk2(a0[k], f0[2*k], f0[2*k+1]);
            upk2(a1[k], f1[2*k], f1[2*k+1]);
        }
        // delta for the two pixels (n = row*64 + 2qx, +1); 64B contiguous/warp
        float* dp = g_delta + ((size_t)(b * 4096 + row * 64 + 2 * qx)) * 8;
#pragma unroll
        for (int j = 0; j < 8; j++) {
            dp[j]     = f0[j] + bias[j];
            dp[8 + j] = f1[j] + bias[j];
        }
#pragma unroll
        for (int j = 0; j < 8; j++)  pphi[j] = fmaxf(pphi[j], fmaxf(f0[8 + j],  f1[8 + j]));
#pragma unroll
        for (int j = 0; j < 32; j++) pg[j]   = fmaxf(pg[j],   fmaxf(f0[16 + j], f1[16 + j]));
    }

    // bias commutes with max (same bias over the window) -> add after pooling
#pragma unroll
    for (int j = 0; j < 8; j++)
        g_phiP[(b * 8 + j) * 1024 + q] = pphi[j] + bias[8 + j];
    float* gp = g_gP + ((size_t)(b * 1024 + q)) * 32;
#pragma unroll
    for (int j = 0; j < 32; j++)
        gp[j] = pg[j] + bias[16 + j];
}

// ---------------------------------------------------------------------------
// Kernel 2: fused attention + final conv + residual.
// grid (8,16): x = query tile (512 queries), y = batch. 256 threads, 2 q/thread.
// Single-pass softmax without max subtraction (scores are O(10), exp safe in fp32).
// ---------------------------------------------------------------------------
__global__ __launch_bounds__(256, 1) void attn_kernel(
    const float* __restrict__ x,
    const float* __restrict__ w_last, const float* __restrict__ b_last,
    const float* __restrict__ gamma,  float* __restrict__ out)
{
    extern __shared__ float sm[];
    float* Vsm = sm;              // 1024*32 = 32768 floats (128 KB)
    float* Ksm = sm + 32768;      // 1024*8  =  8192 floats ( 32 KB)
    float* wl  = sm + 40960;      // 64*32   =  2048 floats (  8 KB)
    float* bl  = sm + 43008;      // 64

    const int tid = threadIdx.x;
    const int b   = blockIdx.y;

    {   // V: [1024][32] straight copy
        const float4* src = (const float4*)(g_gP + (size_t)b * 32768);
        float4* dst = (float4*)Vsm;
        for (int i = tid; i < 8192; i += 256) dst[i] = src[i];
    }
    // K gather with the reference's (1,0,2,3)-transpose batch mixing:
    // K[b][j][m] = phiP[(b*8+j)%16][(b*8+j)/16][m]
#pragma unroll
    for (int j = 0; j < 8; j++) {
        int idx = b * 8 + j;
        const float* src = g_phiP + (size_t)((idx & 15) * 8 + (idx >> 4)) * 1024;
        for (int m = tid; m < 1024; m += 256) Ksm[m * 8 + j] = src[m];
    }
    for (int i = tid; i < 2048; i += 256) wl[i] = w_last[i];
    if (tid < 64) bl[tid] = b_last[tid];
    __syncthreads();

    const int q0 = blockIdx.x * 512 + tid;
    const int q1 = q0 + 256;
    const ulonglong2* dq0 = (const ulonglong2*)(g_delta + ((size_t)b * 4096 + q0) * 8);
    const ulonglong2* dq1 = (const ulonglong2*)(g_delta + ((size_t)b * 4096 + q1) * 8);
    ulonglong2 qa = dq0[0], qb = dq0[1];
    ulonglong2 qc = dq1[0], qd = dq1[1];

    unsigned long long acc0[16], acc1[16];   // 2 x 32 fp32 accumulators as f32x2 pairs
#pragma unroll
    for (int k = 0; k < 16; k++) { acc0[k] = 0ull; acc1[k] = 0ull; }
    float l0 = 0.f, l1 = 0.f;

    const ulonglong2* K2 = (const ulonglong2*)Ksm;
    const ulonglong2* V2 = (const ulonglong2*)Vsm;

#pragma unroll 2
    for (int m = 0; m < 1024; m++) {
        ulonglong2 kA = K2[2 * m], kB = K2[2 * m + 1];   // broadcast LDS.128 x2
        unsigned long long p0 = mul2(qa.x, kA.x);
        p0 = fma2(qa.y, kA.y, p0);
        p0 = fma2(qb.x, kB.x, p0);
        p0 = fma2(qb.y, kB.y, p0);
        unsigned long long p1 = mul2(qc.x, kA.x);
        p1 = fma2(qc.y, kA.y, p1);
        p1 = fma2(qd.x, kB.x, p1);
        p1 = fma2(qd.y, kB.y, p1);
        float s0a, s0b, s1a, s1b;
        upk2(p0, s0a, s0b);
        upk2(p1, s1a, s1b);
        float e0 = __expf(s0a + s0b);
        float e1 = __expf(s1a + s1b);
        l0 += e0; l1 += e1;
        unsigned long long e0p = pk2(e0, e0);
        unsigned long long e1p = pk2(e1, e1);
        const ulonglong2* v = V2 + m * 8;                // broadcast LDS.128 x8
#pragma unroll
        for (int t = 0; t < 8; t++) {
            ulonglong2 vv = v[t];
            acc0[2*t]   = fma2(e0p, vv.x, acc0[2*t]);
            acc0[2*t+1] = fma2(e0p, vv.y, acc0[2*t+1]);
            acc1[2*t]   = fma2(e1p, vv.x, acc1[2*t]);
            acc1[2*t+1] = fma2(e1p, vv.y, acc1[2*t+1]);
        }
    }

    // Fused epilogue: out[b,c,n] = gamma*(dot32(O_n, w_last[c]) + b_last[c]) + x[b,c,n]
    // with O = acc / l  =>  (gamma/l)*dot(acc, w) + gamma*b_last + x
    const float gm  = gamma[0];
    const float gi0 = __fdividef(gm, l0);
    const float gi1 = __fdividef(gm, l1);
    const float* xb = x   + (size_t)b * 262144;
    float*       ob = out + (size_t)b * 262144;
    const ulonglong2* wl2 = (const ulonglong2*)wl;

    for (int c = 0; c < 64; c++) {
        const ulonglong2* wr = wl2 + c * 8;
        ulonglong2 w0 = wr[0];
        unsigned long long s0 = mul2(acc0[0], w0.x);
        unsigned long long s1 = mul2(acc1[0], w0.x);
        s0 = fma2(acc0[1], w0.y, s0);
        s1 = fma2(acc1[1], w0.y, s1);
#pragma unroll
        for (int t = 1; t < 8; t++) {
            ulonglong2 w = wr[t];
            s0 = fma2(acc0[2*t],   w.x, s0);
            s1 = fma2(acc1[2*t],   w.x, s1);
            s0 = fma2(acc0[2*t+1], w.y, s0);
            s1 = fma2(acc1[2*t+1], w.y, s1);
        }
        float r0a, r0b, r1a, r1b;
        upk2(s0, r0a, r0b);
        upk2(s1, r1a, r1b);
        float base = gm * bl[c];
        ob[c * 4096 + q0] = fmaf(gi0, r0a + r0b, base + xb[c * 4096 + q0]);
        ob[c * 4096 + q1] = fmaf(gi1, r1a + r1b, base + xb[c * 4096 + q1]);
    }
}

// ---------------------------------------------------------------------------
extern "C" void kernel_launch(void* const* d_in, const int* in_sizes, int n_in,
                              void* d_out, int out_size)
{
    const float* x  = (const float*)d_in[0];
    const float* wd = (const float*)d_in[1];
    const float* bd = (const float*)d_in[2];
    const float* wp = (const float*)d_in[3];
    const float* bp = (const float*)d_in[4];
    const float* wg = (const float*)d_in[5];
    const float* bg = (const float*)d_in[6];
    const float* wl = (const float*)d_in[7];
    const float* bl = (const float*)d_in[8];
    const float* gm = (const float*)d_in[9];

    conv_pool_kernel<<<dim3(4, 16), 256>>>(x, wd, bd, wp, bp, wg, bg);

    const int shm = (32768 + 8192 + 2048 + 64) * 4;  // 172288 B
    cudaFuncSetAttribute(attn_kernel, cudaFuncAttributeMaxDynamicSharedMemorySize, shm);
    attn_kernel<<<dim3(8, 16), 256, shm>>>(x, wl, bl, gm, (float*)d_out);
}